// round 5
// baseline (speedup 1.0000x reference)
#include <cuda_runtime.h>
#include <cuda_bf16.h>
#include <cuda_fp8.h>
#include <cstdint>

// Problem constants: B=8, N=4096, C=512, K=8192
#define M_TOTAL 32768
#define K_CB    8192
#define C_DIM   512

#define BM 128
#define BN 128
#define BK 64                       // fp8 elements per chunk (64 bytes/row)
#define NCHUNK (C_DIM / BK)         // 8
#define NSTAGE 4
#define ROWPB 80                    // smem pitch in BYTES -> conflict-free ldmatrix
#define MARGIN 24.0f

#define ASZB (BM * ROWPB)           // 10240 bytes per A stage
#define BSZB (BN * ROWPB)           // 10240 bytes per B stage
#define BOFF (NSTAGE * ASZB)        // 40960
#define CSQOFF (BOFF + NSTAGE * BSZB) // 81920
#define SMEM_TOTAL (CSQOFF + BN * 4)  // 82432

// ---------------- device scratch (allocation-free) ----------------
__device__ __align__(16) unsigned char g_xq[(size_t)M_TOTAL * C_DIM];  // 16MB e4m3
__device__ __align__(16) unsigned char g_cbq[(size_t)K_CB * C_DIM];    // 4MB e4m3
__device__ float              g_cbsq[K_CB];
__device__ unsigned long long g_best[M_TOTAL];
__device__ unsigned long long g_blockmin[(size_t)M_TOTAL * (K_CB / 8)]; // 256MB
__device__ int                g_bestk[M_TOTAL];

// ---------------- helpers ----------------
__device__ __forceinline__ uint32_t smem_u32(const void* p) {
    uint32_t a;
    asm("{ .reg .u64 t; cvta.to.shared.u64 t, %1; cvt.u32.u64 %0, t; }" : "=r"(a) : "l"(p));
    return a;
}
__device__ __forceinline__ void cpasync16(uint32_t s, const void* g) {
    asm volatile("{ .reg .u64 gg; cvta.to.global.u64 gg, %1; cp.async.cg.shared.global [%0], [gg], 16; }"
                 :: "r"(s), "l"(g) : "memory");
}
#define CP_COMMIT()  asm volatile("cp.async.commit_group;" ::: "memory")
#define CP_WAIT(n)   asm volatile("cp.async.wait_group %0;" :: "n"(n) : "memory")

__device__ __forceinline__ void ldsm4(uint32_t* r, uint32_t a) {
    asm volatile("ldmatrix.sync.aligned.m8n8.x4.shared.b16 {%0,%1,%2,%3}, [%4];"
                 : "=r"(r[0]), "=r"(r[1]), "=r"(r[2]), "=r"(r[3]) : "r"(a));
}
__device__ __forceinline__ void mma_fp8(float* d, const uint32_t* a, const uint32_t* b) {
    asm volatile("mma.sync.aligned.m16n8k32.row.col.f32.e4m3.e4m3.f32 "
                 "{%0,%1,%2,%3}, {%4,%5,%6,%7}, {%8,%9}, {%0,%1,%2,%3};"
                 : "+f"(d[0]), "+f"(d[1]), "+f"(d[2]), "+f"(d[3])
                 : "r"(a[0]), "r"(a[1]), "r"(a[2]), "r"(a[3]), "r"(b[0]), "r"(b[1]));
}
__device__ __forceinline__ unsigned f2ord(float f) {
    unsigned u = __float_as_uint(f);
    return (u & 0x80000000u) ? ~u : (u | 0x80000000u);
}
__device__ __forceinline__ float ord2f(unsigned o) {
    unsigned u = (o & 0x80000000u) ? (o & 0x7FFFFFFFu) : ~o;
    return __uint_as_float(u);
}
__device__ __forceinline__ unsigned long long u64min(unsigned long long a, unsigned long long b) {
    return a < b ? a : b;
}
__device__ __forceinline__ unsigned f4_to_e4m3x4(float4 v) {
    unsigned lo = __nv_cvt_float2_to_fp8x2(make_float2(v.x, v.y), __NV_SATFINITE, __NV_E4M3);
    unsigned hi = __nv_cvt_float2_to_fp8x2(make_float2(v.z, v.w), __NV_SATFINITE, __NV_E4M3);
    return lo | (hi << 16);
}

// ---------------------------------------------------------------------------
// fp32 -> e4m3 pre-convert of X and codebook
// ---------------------------------------------------------------------------
__global__ void convert_kernel(const float* __restrict__ X, const float* __restrict__ CB) {
    const long NX = (long)M_TOTAL * C_DIM / 4;
    const long NC = (long)K_CB * C_DIM / 4;
    long i = (long)blockIdx.x * blockDim.x + threadIdx.x;
    if (i < NX) {
        ((unsigned*)g_xq)[i] = f4_to_e4m3x4(((const float4*)X)[i]);
    } else if (i < NX + NC) {
        long j = i - NX;
        ((unsigned*)g_cbq)[j] = f4_to_e4m3x4(((const float4*)CB)[j]);
    }
}

__global__ void cbsq_kernel(const float* __restrict__ cb) {
    int row = blockIdx.x * 8 + (threadIdx.x >> 5);
    int lane = threadIdx.x & 31;
    const float* r = cb + (size_t)row * C_DIM;
    float s = 0.f;
    #pragma unroll
    for (int c = lane; c < C_DIM; c += 32) { float v = r[c]; s = fmaf(v, v, s); }
    #pragma unroll
    for (int o = 16; o; o >>= 1) s += __shfl_xor_sync(0xffffffffu, s, o);
    if (lane == 0) g_cbsq[row] = s;
}

__global__ void init_kernel() {
    int i = blockIdx.x * blockDim.x + threadIdx.x;
    if (i < M_TOTAL) g_best[i] = 0xFFFFFFFFFFFFFFFFULL;
}

// ---------------------------------------------------------------------------
// Coarse e4m3 HMMA GEMM + per-8 block-min epilogue
//   8 warps 2(M)x4(N), warp tile 64x32, mma m16n8k32, 4-stage cp.async
// ---------------------------------------------------------------------------
__global__ void __launch_bounds__(256, 2) gemm_kernel() {
    extern __shared__ __align__(16) char smem[];
    const uint32_t sb = smem_u32(smem);
    float* s_csq = (float*)(smem + CSQOFF);

    const int tid  = threadIdx.x;
    const int wid  = tid >> 5, lane = tid & 31;
    const int wy   = wid >> 2, wx = wid & 3;
    const int m0   = wy * 64,  n0 = wx * 32;
    const int mbase = blockIdx.y * BM;
    const int nbase = blockIdx.x * BN;

    if (tid < BN) s_csq[tid] = g_cbsq[nbase + tid];

    float acc[4][4][4];
    #pragma unroll
    for (int i = 0; i < 4; i++)
        #pragma unroll
        for (int j = 0; j < 4; j++)
            #pragma unroll
            for (int q = 0; q < 4; q++) acc[i][j][q] = 0.f;

    // ldmatrix lane addressing (byte offsets; 16B k-halves)
    const int a_row  = (lane & 7) + ((lane >> 3) & 1) * 8;
    const int a_colb = (lane >> 4) * 16;
    const int b_row  = (lane & 7) + (lane >> 4) * 8;
    const int b_colb = ((lane >> 3) & 1) * 16;

    uint32_t aBase[NSTAGE], bBase[NSTAGE];
    #pragma unroll
    for (int s = 0; s < NSTAGE; s++) {
        aBase[s] = sb + s * ASZB + (uint32_t)((m0 + a_row) * ROWPB + a_colb);
        bBase[s] = sb + BOFF + s * BSZB + (uint32_t)((n0 + b_row) * ROWPB + b_colb);
    }

    // cp.async loader: 512 16B segments per operand per chunk, 2 passes
    const int ld_row = tid >> 1;                 // 0..127
    const int ld_seg = (tid & 1) * 2;            // 0 or 2 (two segs each pass)
    auto load_chunk = [&](int s, int cc) {
        const uint32_t soA = sb + s * ASZB + (uint32_t)(ld_row * ROWPB + ld_seg * 16);
        const uint32_t soB = sb + BOFF + s * BSZB + (uint32_t)(ld_row * ROWPB + ld_seg * 16);
        const unsigned char* gA = g_xq + (size_t)(mbase + ld_row) * C_DIM + cc + ld_seg * 16;
        const unsigned char* gB = g_cbq + (size_t)(nbase + ld_row) * C_DIM + cc + ld_seg * 16;
        cpasync16(soA, gA);      cpasync16(soA + 16, gA + 16);
        cpasync16(soB, gB);      cpasync16(soB + 16, gB + 16);
    };

    load_chunk(0, 0); CP_COMMIT();
    load_chunk(1, BK); CP_COMMIT();
    load_chunk(2, 2 * BK); CP_COMMIT();

    for (int cb = 0; cb < NCHUNK; cb += NSTAGE) {
        #pragma unroll
        for (int i = 0; i < NSTAGE; i++) {
            const int ch = cb + i;
            if (ch < NCHUNK - 2)      { CP_WAIT(2); }
            else if (ch == NCHUNK - 2){ CP_WAIT(1); }
            else                      { CP_WAIT(0); }
            __syncthreads();
            if (ch + 3 < NCHUNK) { load_chunk((ch + 3) & 3, (ch + 3) * BK); CP_COMMIT(); }

            const uint32_t aS = aBase[i], bS = bBase[i];
            #pragma unroll
            for (int ks = 0; ks < 2; ks++) {         // two k32 steps per 64B chunk
                uint32_t a[4][4];
                #pragma unroll
                for (int mf = 0; mf < 4; mf++)
                    ldsm4(a[mf], aS + (uint32_t)(mf * 16 * ROWPB) + ks * 32);
                uint32_t b[4][2];
                #pragma unroll
                for (int np = 0; np < 2; np++) {
                    uint32_t r[4];
                    ldsm4(r, bS + (uint32_t)(np * 16 * ROWPB) + ks * 32);
                    b[np * 2 + 0][0] = r[0]; b[np * 2 + 0][1] = r[1];
                    b[np * 2 + 1][0] = r[2]; b[np * 2 + 1][1] = r[3];
                }
                #pragma unroll
                for (int mf = 0; mf < 4; mf++)
                    #pragma unroll
                    for (int nf = 0; nf < 4; nf++)
                        mma_fp8(acc[mf][nf], a[mf], b[nf]);
            }
        }
    }

    // ---- epilogue: scores, packed 8-col block-mins, per-row global best ----
    const int qrow = lane >> 2;
    const int qcol = (lane & 3) * 2;
    #pragma unroll
    for (int mf = 0; mf < 4; mf++) {
        const int row0 = mbase + m0 + mf * 16 + qrow;
        unsigned long long rb0 = 0xFFFFFFFFFFFFFFFFULL;
        unsigned long long rb1 = 0xFFFFFFFFFFFFFFFFULL;
        #pragma unroll
        for (int nf = 0; nf < 4; nf++) {
            const int cb_loc = n0 + nf * 8 + qcol;
            const int cb_abs = nbase + cb_loc;
            const float cs0 = s_csq[cb_loc], cs1 = s_csq[cb_loc + 1];
            float s00 = fmaf(2.f, acc[mf][nf][0], cs0);
            float s01 = fmaf(2.f, acc[mf][nf][1], cs1);
            float s10 = fmaf(2.f, acc[mf][nf][2], cs0);
            float s11 = fmaf(2.f, acc[mf][nf][3], cs1);
            unsigned long long p0 =
                u64min(((unsigned long long)f2ord(s00) << 32) | (unsigned)cb_abs,
                       ((unsigned long long)f2ord(s01) << 32) | (unsigned)(cb_abs + 1));
            unsigned long long p1 =
                u64min(((unsigned long long)f2ord(s10) << 32) | (unsigned)cb_abs,
                       ((unsigned long long)f2ord(s11) << 32) | (unsigned)(cb_abs + 1));
            #pragma unroll
            for (int o = 1; o <= 2; o <<= 1) {
                p0 = u64min(p0, __shfl_xor_sync(0xffffffffu, p0, o));
                p1 = u64min(p1, __shfl_xor_sync(0xffffffffu, p1, o));
            }
            if ((lane & 3) == 0) {
                const int blk = (nbase + n0 + nf * 8) >> 3;
                __stcs(&g_blockmin[(size_t)row0 * (K_CB / 8) + blk], p0);
                __stcs(&g_blockmin[(size_t)(row0 + 8) * (K_CB / 8) + blk], p1);
                rb0 = u64min(rb0, p0);
                rb1 = u64min(rb1, p1);
            }
        }
        if ((lane & 3) == 0) {
            atomicMin(&g_best[row0], rb0);
            atomicMin(&g_best[row0 + 8], rb1);
        }
    }
}

// ---------------------------------------------------------------------------
// Exact fp32 rescue — one warp per row
// ---------------------------------------------------------------------------
__global__ void __launch_bounds__(256) rescue_kernel(const float* __restrict__ X,
                                                     const float* __restrict__ CB) {
    const int row = blockIdx.x * 8 + (threadIdx.x >> 5);
    const int lane = threadIdx.x & 31;

    float x[16];
    {
        const float4* xr = (const float4*)(X + (size_t)row * C_DIM + lane * 16);
        float4 a = xr[0], b = xr[1], c = xr[2], d = xr[3];
        x[0]=a.x; x[1]=a.y; x[2]=a.z; x[3]=a.w; x[4]=b.x; x[5]=b.y; x[6]=b.z; x[7]=b.w;
        x[8]=c.x; x[9]=c.y; x[10]=c.z; x[11]=c.w; x[12]=d.x; x[13]=d.y; x[14]=d.z; x[15]=d.w;
    }

    const unsigned long long gb = g_best[row];
    const float s1 = ord2f((unsigned)(gb >> 32));
    const unsigned thr = f2ord(s1 + MARGIN);

    float bests = 3.4e38f; int bestk = 0x7FFFFFFF;
    const unsigned long long* bm = g_blockmin + (size_t)row * (K_CB / 8);

    for (int r = 0; r < 32; r++) {
        unsigned long long v = __ldcs(&bm[r * 32 + lane]);
        unsigned mask = __ballot_sync(0xffffffffu, (unsigned)(v >> 32) <= thr);
        while (mask) {
            int b = __ffs(mask) - 1;
            mask &= mask - 1;
            int k0 = (r * 32 + b) * 8;
            #pragma unroll
            for (int j = 0; j < 8; j++) {
                int k = k0 + j;
                const float4* cr = (const float4*)(CB + (size_t)k * C_DIM + lane * 16);
                float4 c0 = cr[0], c1 = cr[1], c2 = cr[2], c3 = cr[3];
                float p = 0.f;
                p = fmaf(x[0],  c0.x, p); p = fmaf(x[1],  c0.y, p);
                p = fmaf(x[2],  c0.z, p); p = fmaf(x[3],  c0.w, p);
                p = fmaf(x[4],  c1.x, p); p = fmaf(x[5],  c1.y, p);
                p = fmaf(x[6],  c1.z, p); p = fmaf(x[7],  c1.w, p);
                p = fmaf(x[8],  c2.x, p); p = fmaf(x[9],  c2.y, p);
                p = fmaf(x[10], c2.z, p); p = fmaf(x[11], c2.w, p);
                p = fmaf(x[12], c3.x, p); p = fmaf(x[13], c3.y, p);
                p = fmaf(x[14], c3.z, p); p = fmaf(x[15], c3.w, p);
                #pragma unroll
                for (int o = 16; o; o >>= 1) p += __shfl_xor_sync(0xffffffffu, p, o);
                float s = fmaf(2.f, p, __ldg(&g_cbsq[k]));
                if (s < bests || (s == bests && k < bestk)) { bests = s; bestk = k; }
            }
        }
    }
    if (lane == 0) g_bestk[row] = bestk;
}

// ---------------------------------------------------------------------------
__global__ void gather_kernel(const float* __restrict__ CB,
                              float* __restrict__ out, int out_size) {
    const int row = blockIdx.x;
    const int k = g_bestk[row];
    const size_t BNC = (size_t)M_TOTAL * C_DIM;

    float4 v = ((const float4*)(CB + (size_t)k * C_DIM))[threadIdx.x];
    ((float4*)(out + (size_t)row * C_DIM))[threadIdx.x] = v;
    if ((size_t)out_size >= 2 * BNC)
        ((float4*)(out + BNC + (size_t)row * C_DIM))[threadIdx.x] = v;
    if (threadIdx.x == 0 && (size_t)out_size >= 2 * BNC + M_TOTAL)
        out[2 * BNC + row] = (float)k;
}

// ---------------------------------------------------------------------------
extern "C" void kernel_launch(void* const* d_in, const int* in_sizes, int n_in,
                              void* d_out, int out_size) {
    const float* X  = (const float*)d_in[0];
    const float* CB = (const float*)d_in[1];
    if (n_in >= 2 && in_sizes[0] == K_CB * C_DIM && in_sizes[1] == M_TOTAL * C_DIM) {
        X  = (const float*)d_in[1];
        CB = (const float*)d_in[0];
    }
    float* out = (float*)d_out;

    static bool attr_set = false;
    if (!attr_set) {
        cudaFuncSetAttribute(gemm_kernel, cudaFuncAttributeMaxDynamicSharedMemorySize, SMEM_TOTAL);
        attr_set = true;
    }

    const long nconv = ((long)M_TOTAL * C_DIM + (long)K_CB * C_DIM) / 4;
    convert_kernel<<<(unsigned)((nconv + 255) / 256), 256>>>(X, CB);
    cbsq_kernel<<<K_CB / 8, 256>>>(CB);
    init_kernel<<<(M_TOTAL + 255) / 256, 256>>>();
    gemm_kernel<<<dim3(K_CB / BN, M_TOTAL / BM), 256, SMEM_TOTAL>>>();
    rescue_kernel<<<M_TOTAL / 8, 256>>>(X, CB);
    gather_kernel<<<M_TOTAL, 128>>>(CB, out, out_size);
}

// round 7
// speedup vs baseline: 1.0107x; 1.0107x over previous
#include <cuda_runtime.h>
#include <cuda_bf16.h>
#include <cstdint>

// Problem constants: B=8, N=4096, C=512, K=8192
#define M_TOTAL 32768
#define K_CB    8192
#define C_DIM   512

#define BM 128
#define BN 256
#define BK 64                        // bf16 elems per chunk (128B per row)
#define NCHUNK (C_DIM / BK)          // 8
#define NSTAGE 3
#define ROWPB 144                    // bytes per row (128B data + 16B skew)
#define MARGIN 4.0f

#define ASZB (BM * ROWPB)            // 18432
#define BSZB (BN * ROWPB)            // 36864
#define BOFF (NSTAGE * ASZB)         // 55296
#define CSQOFF (BOFF + NSTAGE * BSZB) // 165888
#define SMEM_TOTAL (CSQOFF + BN * 4)  // 166912

// ---------------- device scratch (allocation-free) ----------------
__device__ __nv_bfloat16      g_xb[(size_t)M_TOTAL * C_DIM];   // 32MB
__device__ __nv_bfloat16      g_cbb[(size_t)K_CB * C_DIM];     // 8MB
__device__ float              g_cbsq[K_CB];
__device__ unsigned long long g_best[M_TOTAL];
__device__ unsigned long long g_blockmin[(size_t)M_TOTAL * (K_CB / 8)]; // 256MB
__device__ int                g_bestk[M_TOTAL];

// ---------------- helpers ----------------
__device__ __forceinline__ uint32_t smem_u32(const void* p) {
    uint32_t a;
    asm("{ .reg .u64 t; cvta.to.shared.u64 t, %1; cvt.u32.u64 %0, t; }" : "=r"(a) : "l"(p));
    return a;
}
__device__ __forceinline__ void cpasync16(uint32_t s, const void* g) {
    asm volatile("{ .reg .u64 gg; cvta.to.global.u64 gg, %1; cp.async.cg.shared.global [%0], [gg], 16; }"
                 :: "r"(s), "l"(g) : "memory");
}
#define CP_COMMIT()  asm volatile("cp.async.commit_group;" ::: "memory")
#define CP_WAIT(n)   asm volatile("cp.async.wait_group %0;" :: "n"(n) : "memory")

__device__ __forceinline__ void ldsm4(uint32_t* r, uint32_t a) {
    asm volatile("ldmatrix.sync.aligned.m8n8.x4.shared.b16 {%0,%1,%2,%3}, [%4];"
                 : "=r"(r[0]), "=r"(r[1]), "=r"(r[2]), "=r"(r[3]) : "r"(a));
}
__device__ __forceinline__ void mma16816(float* d, const uint32_t* a, const uint32_t* b) {
    asm volatile("mma.sync.aligned.m16n8k16.row.col.f32.bf16.bf16.f32 "
                 "{%0,%1,%2,%3}, {%4,%5,%6,%7}, {%8,%9}, {%0,%1,%2,%3};"
                 : "+f"(d[0]), "+f"(d[1]), "+f"(d[2]), "+f"(d[3])
                 : "r"(a[0]), "r"(a[1]), "r"(a[2]), "r"(a[3]), "r"(b[0]), "r"(b[1]));
}
__device__ __forceinline__ unsigned f2ord(float f) {
    unsigned u = __float_as_uint(f);
    return (u & 0x80000000u) ? ~u : (u | 0x80000000u);
}
__device__ __forceinline__ float ord2f(unsigned o) {
    unsigned u = (o & 0x80000000u) ? (o & 0x7FFFFFFFu) : ~o;
    return __uint_as_float(u);
}
__device__ __forceinline__ unsigned long long u64min(unsigned long long a, unsigned long long b) {
    return a < b ? a : b;
}

// ---------------------------------------------------------------------------
__global__ void convert_kernel(const float* __restrict__ X, const float* __restrict__ CB) {
    const long NX = (long)M_TOTAL * C_DIM / 4;
    const long NC = (long)K_CB * C_DIM / 4;
    long i = (long)blockIdx.x * blockDim.x + threadIdx.x;
    if (i < NX) {
        float4 v = ((const float4*)X)[i];
        __nv_bfloat162* o = (__nv_bfloat162*)g_xb;
        o[2 * i]     = __floats2bfloat162_rn(v.x, v.y);
        o[2 * i + 1] = __floats2bfloat162_rn(v.z, v.w);
    } else if (i < NX + NC) {
        long j = i - NX;
        float4 v = ((const float4*)CB)[j];
        __nv_bfloat162* o = (__nv_bfloat162*)g_cbb;
        o[2 * j]     = __floats2bfloat162_rn(v.x, v.y);
        o[2 * j + 1] = __floats2bfloat162_rn(v.z, v.w);
    }
}

__global__ void cbsq_kernel(const float* __restrict__ cb) {
    int row = blockIdx.x * 8 + (threadIdx.x >> 5);
    int lane = threadIdx.x & 31;
    const float* r = cb + (size_t)row * C_DIM;
    float s = 0.f;
    #pragma unroll
    for (int c = lane; c < C_DIM; c += 32) { float v = r[c]; s = fmaf(v, v, s); }
    #pragma unroll
    for (int o = 16; o; o >>= 1) s += __shfl_xor_sync(0xffffffffu, s, o);
    if (lane == 0) g_cbsq[row] = s;
}

__global__ void init_kernel() {
    int i = blockIdx.x * blockDim.x + threadIdx.x;
    if (i < M_TOTAL) g_best[i] = 0xFFFFFFFFFFFFFFFFULL;
}

// ---------------------------------------------------------------------------
// Coarse bf16 HMMA GEMM + per-8 block-min epilogue
//   CTA 128x256, 8 warps 2(M)x4(N), warp tile 64x64, BK=64, 3-stage cp.async
// ---------------------------------------------------------------------------
__global__ void __launch_bounds__(256, 1) gemm_kernel() {
    extern __shared__ __align__(16) char smem[];
    const uint32_t sb = smem_u32(smem);
    float* s_csq = (float*)(smem + CSQOFF);

    const int tid  = threadIdx.x;
    const int wid  = tid >> 5, lane = tid & 31;
    const int wy   = wid >> 2, wx = wid & 3;
    const int m0   = wy * 64,  n0 = wx * 64;
    const int mbase = blockIdx.y * BM;
    const int nbase = blockIdx.x * BN;

    s_csq[tid] = g_cbsq[nbase + tid];

    float acc[4][8][4];
    #pragma unroll
    for (int i = 0; i < 4; i++)
        #pragma unroll
        for (int j = 0; j < 8; j++)
            #pragma unroll
            for (int q = 0; q < 4; q++) acc[i][j][q] = 0.f;

    // ldmatrix lane addressing (byte offsets) — proven mapping from R3/R4
    const int a_row  = (lane & 7) + ((lane >> 3) & 1) * 8;
    const int a_colb = (lane >> 4) * 16;
    const int b_row  = (lane & 7) + (lane >> 4) * 8;
    const int b_colb = ((lane >> 3) & 1) * 16;

    uint32_t aBase[NSTAGE], bBase[NSTAGE];
    #pragma unroll
    for (int s = 0; s < NSTAGE; s++) {
        aBase[s] = sb + s * ASZB + (uint32_t)((m0 + a_row) * ROWPB + a_colb);
        bBase[s] = sb + BOFF + s * BSZB + (uint32_t)((n0 + b_row) * ROWPB + b_colb);
    }

    // cp.async loader (FIXED for 128B rows):
    //   A: 128 rows x 128B; 2 threads/row, 64B (4x16B) each
    //   B: 256 rows x 128B; same pattern over two 128-row halves
    const int ld_row = tid >> 1;                 // 0..127
    const int ld_off = (tid & 1) * 64;           // byte offset within row: 0 or 64
    auto load_chunk = [&](int s, int cc) {
        const uint32_t soA = sb + s * ASZB + (uint32_t)(ld_row * ROWPB + ld_off);
        const uint32_t soB = sb + BOFF + s * BSZB + (uint32_t)(ld_row * ROWPB + ld_off);
        const __nv_bfloat16* gA = g_xb + (size_t)(mbase + ld_row) * C_DIM + cc + ld_off / 2;
        const __nv_bfloat16* gB = g_cbb + (size_t)(nbase + ld_row) * C_DIM + cc + ld_off / 2;
        #pragma unroll
        for (int q = 0; q < 4; q++) {
            cpasync16(soA + q * 16, gA + q * 8);
            cpasync16(soB + q * 16, gB + q * 8);
            cpasync16(soB + (uint32_t)(128 * ROWPB) + q * 16, gB + (size_t)128 * C_DIM + q * 8);
        }
    };

    load_chunk(0, 0); CP_COMMIT();
    load_chunk(1, BK); CP_COMMIT();

    #pragma unroll
    for (int ch = 0; ch < NCHUNK; ch++) {
        if (ch < NCHUNK - 1) { CP_WAIT(1); } else { CP_WAIT(0); }
        __syncthreads();
        if (ch + 2 < NCHUNK) { load_chunk((ch + 2) % NSTAGE, (ch + 2) * BK); CP_COMMIT(); }

        const uint32_t aS = aBase[ch % NSTAGE], bS = bBase[ch % NSTAGE];
        #pragma unroll
        for (int ks = 0; ks < 4; ks++) {            // four k16 steps per 64-elem chunk
            uint32_t a[4][4];
            #pragma unroll
            for (int mf = 0; mf < 4; mf++)
                ldsm4(a[mf], aS + (uint32_t)(mf * 16 * ROWPB) + ks * 32);
            uint32_t b[8][2];
            #pragma unroll
            for (int np = 0; np < 4; np++) {
                uint32_t r[4];
                ldsm4(r, bS + (uint32_t)(np * 16 * ROWPB) + ks * 32);
                b[np * 2 + 0][0] = r[0]; b[np * 2 + 0][1] = r[1];
                b[np * 2 + 1][0] = r[2]; b[np * 2 + 1][1] = r[3];
            }
            #pragma unroll
            for (int mf = 0; mf < 4; mf++)
                #pragma unroll
                for (int nf = 0; nf < 8; nf++)
                    mma16816(acc[mf][nf], a[mf], b[nf]);
        }
    }

    // ---- epilogue: scores, packed 8-col block-mins, per-row global best ----
    const int qrow = lane >> 2;
    const int qcol = (lane & 3) * 2;
    #pragma unroll
    for (int mf = 0; mf < 4; mf++) {
        const int row0 = mbase + m0 + mf * 16 + qrow;
        unsigned long long rb0 = 0xFFFFFFFFFFFFFFFFULL;
        unsigned long long rb1 = 0xFFFFFFFFFFFFFFFFULL;
        #pragma unroll
        for (int nf = 0; nf < 8; nf++) {
            const int cb_loc = n0 + nf * 8 + qcol;
            const int cb_abs = nbase + cb_loc;
            const float cs0 = s_csq[cb_loc], cs1 = s_csq[cb_loc + 1];
            float s00 = fmaf(2.f, acc[mf][nf][0], cs0);
            float s01 = fmaf(2.f, acc[mf][nf][1], cs1);
            float s10 = fmaf(2.f, acc[mf][nf][2], cs0);
            float s11 = fmaf(2.f, acc[mf][nf][3], cs1);
            unsigned long long p0 =
                u64min(((unsigned long long)f2ord(s00) << 32) | (unsigned)cb_abs,
                       ((unsigned long long)f2ord(s01) << 32) | (unsigned)(cb_abs + 1));
            unsigned long long p1 =
                u64min(((unsigned long long)f2ord(s10) << 32) | (unsigned)cb_abs,
                       ((unsigned long long)f2ord(s11) << 32) | (unsigned)(cb_abs + 1));
            #pragma unroll
            for (int o = 1; o <= 2; o <<= 1) {
                p0 = u64min(p0, __shfl_xor_sync(0xffffffffu, p0, o));
                p1 = u64min(p1, __shfl_xor_sync(0xffffffffu, p1, o));
            }
            if ((lane & 3) == 0) {
                const int blk = (nbase + n0 + nf * 8) >> 3;
                __stcs(&g_blockmin[(size_t)row0 * (K_CB / 8) + blk], p0);
                __stcs(&g_blockmin[(size_t)(row0 + 8) * (K_CB / 8) + blk], p1);
                rb0 = u64min(rb0, p0);
                rb1 = u64min(rb1, p1);
            }
        }
        if ((lane & 3) == 0) {
            atomicMin(&g_best[row0], rb0);
            atomicMin(&g_best[row0 + 8], rb1);
        }
    }
}

// ---------------------------------------------------------------------------
// Exact fp32 rescue — one warp per row
// ---------------------------------------------------------------------------
__global__ void __launch_bounds__(256) rescue_kernel(const float* __restrict__ X,
                                                     const float* __restrict__ CB) {
    const int row = blockIdx.x * 8 + (threadIdx.x >> 5);
    const int lane = threadIdx.x & 31;

    float x[16];
    {
        const float4* xr = (const float4*)(X + (size_t)row * C_DIM + lane * 16);
        float4 a = xr[0], b = xr[1], c = xr[2], d = xr[3];
        x[0]=a.x; x[1]=a.y; x[2]=a.z; x[3]=a.w; x[4]=b.x; x[5]=b.y; x[6]=b.z; x[7]=b.w;
        x[8]=c.x; x[9]=c.y; x[10]=c.z; x[11]=c.w; x[12]=d.x; x[13]=d.y; x[14]=d.z; x[15]=d.w;
    }

    const unsigned long long gb = g_best[row];
    const float s1 = ord2f((unsigned)(gb >> 32));
    const unsigned thr = f2ord(s1 + MARGIN);

    float bests = 3.4e38f; int bestk = 0x7FFFFFFF;
    const unsigned long long* bm = g_blockmin + (size_t)row * (K_CB / 8);

    for (int r = 0; r < 32; r++) {
        unsigned long long v = __ldcs(&bm[r * 32 + lane]);
        unsigned mask = __ballot_sync(0xffffffffu, (unsigned)(v >> 32) <= thr);
        while (mask) {
            int b = __ffs(mask) - 1;
            mask &= mask - 1;
            int k0 = (r * 32 + b) * 8;
            #pragma unroll
            for (int j = 0; j < 8; j++) {
                int k = k0 + j;
                const float4* cr = (const float4*)(CB + (size_t)k * C_DIM + lane * 16);
                float4 c0 = cr[0], c1 = cr[1], c2 = cr[2], c3 = cr[3];
                float p = 0.f;
                p = fmaf(x[0],  c0.x, p); p = fmaf(x[1],  c0.y, p);
                p = fmaf(x[2],  c0.z, p); p = fmaf(x[3],  c0.w, p);
                p = fmaf(x[4],  c1.x, p); p = fmaf(x[5],  c1.y, p);
                p = fmaf(x[6],  c1.z, p); p = fmaf(x[7],  c1.w, p);
                p = fmaf(x[8],  c2.x, p); p = fmaf(x[9],  c2.y, p);
                p = fmaf(x[10], c2.z, p); p = fmaf(x[11], c2.w, p);
                p = fmaf(x[12], c3.x, p); p = fmaf(x[13], c3.y, p);
                p = fmaf(x[14], c3.z, p); p = fmaf(x[15], c3.w, p);
                #pragma unroll
                for (int o = 16; o; o >>= 1) p += __shfl_xor_sync(0xffffffffu, p, o);
                float s = fmaf(2.f, p, __ldg(&g_cbsq[k]));
                if (s < bests || (s == bests && k < bestk)) { bests = s; bestk = k; }
            }
        }
    }
    if (lane == 0) g_bestk[row] = bestk;
}

// ---------------------------------------------------------------------------
__global__ void gather_kernel(const float* __restrict__ CB,
                              float* __restrict__ out, int out_size) {
    const int row = blockIdx.x;
    const int k = g_bestk[row];
    const size_t BNC = (size_t)M_TOTAL * C_DIM;

    float4 v = ((const float4*)(CB + (size_t)k * C_DIM))[threadIdx.x];
    ((float4*)(out + (size_t)row * C_DIM))[threadIdx.x] = v;
    if ((size_t)out_size >= 2 * BNC)
        ((float4*)(out + BNC + (size_t)row * C_DIM))[threadIdx.x] = v;
    if (threadIdx.x == 0 && (size_t)out_size >= 2 * BNC + M_TOTAL)
        out[2 * BNC + row] = (float)k;
}

// ---------------------------------------------------------------------------
extern "C" void kernel_launch(void* const* d_in, const int* in_sizes, int n_in,
                              void* d_out, int out_size) {
    const float* X  = (const float*)d_in[0];
    const float* CB = (const float*)d_in[1];
    if (n_in >= 2 && in_sizes[0] == K_CB * C_DIM && in_sizes[1] == M_TOTAL * C_DIM) {
        X  = (const float*)d_in[1];
        CB = (const float*)d_in[0];
    }
    float* out = (float*)d_out;

    static bool attr_set = false;
    if (!attr_set) {
        cudaFuncSetAttribute(gemm_kernel, cudaFuncAttributeMaxDynamicSharedMemorySize, SMEM_TOTAL);
        attr_set = true;
    }

    const long nconv = ((long)M_TOTAL * C_DIM + (long)K_CB * C_DIM) / 4;
    convert_kernel<<<(unsigned)((nconv + 255) / 256), 256>>>(X, CB);
    cbsq_kernel<<<K_CB / 8, 256>>>(CB);
    init_kernel<<<(M_TOTAL + 255) / 256, 256>>>();
    gemm_kernel<<<dim3(K_CB / BN, M_TOTAL / BM), 256, SMEM_TOTAL>>>();
    rescue_kernel<<<M_TOTAL / 8, 256>>>(X, CB);
    gather_kernel<<<M_TOTAL, 128>>>(CB, out, out_size);
}

// round 8
// speedup vs baseline: 1.1026x; 1.0910x over previous
#include <cuda_runtime.h>
#include <cuda_bf16.h>
#include <cstdint>

// Problem constants: B=8, N=4096, C=512, K=8192
#define M_TOTAL 32768
#define K_CB    8192
#define C_DIM   512

#define BM 128
#define BN 128
#define BK 64                        // bf16 elems per chunk (128B per row)
#define NCHUNK (C_DIM / BK)          // 8
#define NSTAGE 3
#define ROWPB 144                    // bytes per row (128B data + 16B skew)
#define MARGIN 4.0f

#define ASZB (BM * ROWPB)            // 18432
#define BSZB (BN * ROWPB)            // 18432
#define STGB (ASZB + BSZB)           // 36864 per stage
#define CSQOFF (NSTAGE * STGB)       // 110592
#define SMEM_TOTAL (CSQOFF + BN * 4) // 111104

// ---------------- device scratch (allocation-free) ----------------
__device__ __nv_bfloat16 g_xb[(size_t)M_TOTAL * C_DIM];   // 32MB
__device__ __nv_bfloat16 g_cbb[(size_t)K_CB * C_DIM];     // 8MB
__device__ float         g_cbsq[K_CB];
__device__ unsigned      g_best[M_TOTAL];                  // ord(best approx score)
__device__ unsigned      g_blockmin[(size_t)M_TOTAL * (K_CB / 8)]; // 128MB ord scores
__device__ int           g_bestk[M_TOTAL];

// ---------------- helpers ----------------
__device__ __forceinline__ uint32_t smem_u32(const void* p) {
    uint32_t a;
    asm("{ .reg .u64 t; cvta.to.shared.u64 t, %1; cvt.u32.u64 %0, t; }" : "=r"(a) : "l"(p));
    return a;
}
__device__ __forceinline__ void cpasync16(uint32_t s, const void* g) {
    asm volatile("{ .reg .u64 gg; cvta.to.global.u64 gg, %1; cp.async.cg.shared.global [%0], [gg], 16; }"
                 :: "r"(s), "l"(g) : "memory");
}
#define CP_COMMIT()  asm volatile("cp.async.commit_group;" ::: "memory")
#define CP_WAIT(n)   asm volatile("cp.async.wait_group %0;" :: "n"(n) : "memory")

__device__ __forceinline__ void ldsm4(uint32_t* r, uint32_t a) {
    asm volatile("ldmatrix.sync.aligned.m8n8.x4.shared.b16 {%0,%1,%2,%3}, [%4];"
                 : "=r"(r[0]), "=r"(r[1]), "=r"(r[2]), "=r"(r[3]) : "r"(a));
}
__device__ __forceinline__ void mma16816(float* d, const uint32_t* a, const uint32_t* b) {
    asm volatile("mma.sync.aligned.m16n8k16.row.col.f32.bf16.bf16.f32 "
                 "{%0,%1,%2,%3}, {%4,%5,%6,%7}, {%8,%9}, {%0,%1,%2,%3};"
                 : "+f"(d[0]), "+f"(d[1]), "+f"(d[2]), "+f"(d[3])
                 : "r"(a[0]), "r"(a[1]), "r"(a[2]), "r"(a[3]), "r"(b[0]), "r"(b[1]));
}
__device__ __forceinline__ unsigned f2ord(float f) {
    unsigned u = __float_as_uint(f);
    return (u & 0x80000000u) ? ~u : (u | 0x80000000u);
}
__device__ __forceinline__ float ord2f(unsigned o) {
    unsigned u = (o & 0x80000000u) ? (o & 0x7FFFFFFFu) : ~o;
    return __uint_as_float(u);
}
__device__ __forceinline__ unsigned umin2(unsigned a, unsigned b) { return a < b ? a : b; }

// ---------------------------------------------------------------------------
__global__ void convert_kernel(const float* __restrict__ X, const float* __restrict__ CB) {
    const long NX = (long)M_TOTAL * C_DIM / 4;
    const long NC = (long)K_CB * C_DIM / 4;
    long i = (long)blockIdx.x * blockDim.x + threadIdx.x;
    if (i < NX) {
        float4 v = ((const float4*)X)[i];
        __nv_bfloat162* o = (__nv_bfloat162*)g_xb;
        o[2 * i]     = __floats2bfloat162_rn(v.x, v.y);
        o[2 * i + 1] = __floats2bfloat162_rn(v.z, v.w);
    } else if (i < NX + NC) {
        long j = i - NX;
        float4 v = ((const float4*)CB)[j];
        __nv_bfloat162* o = (__nv_bfloat162*)g_cbb;
        o[2 * j]     = __floats2bfloat162_rn(v.x, v.y);
        o[2 * j + 1] = __floats2bfloat162_rn(v.z, v.w);
    }
}

__global__ void cbsq_kernel(const float* __restrict__ cb) {
    int row = blockIdx.x * 8 + (threadIdx.x >> 5);
    int lane = threadIdx.x & 31;
    const float* r = cb + (size_t)row * C_DIM;
    float s = 0.f;
    #pragma unroll
    for (int c = lane; c < C_DIM; c += 32) { float v = r[c]; s = fmaf(v, v, s); }
    #pragma unroll
    for (int o = 16; o; o >>= 1) s += __shfl_xor_sync(0xffffffffu, s, o);
    if (lane == 0) g_cbsq[row] = s;
}

__global__ void init_kernel() {
    int i = blockIdx.x * blockDim.x + threadIdx.x;
    if (i < M_TOTAL) g_best[i] = 0xFFFFFFFFu;
}

// ---------------------------------------------------------------------------
// Coarse bf16 HMMA GEMM + per-8 block-min epilogue
//   CTA 128x128, 8 warps 2(M)x4(N), warp tile 64x32, BK=64, 3 stages, 2 CTAs/SM
// ---------------------------------------------------------------------------
__global__ void __launch_bounds__(256, 2) gemm_kernel() {
    extern __shared__ __align__(16) char smem[];
    const uint32_t sb = smem_u32(smem);
    float* s_csq = (float*)(smem + CSQOFF);

    const int tid  = threadIdx.x;
    const int wid  = tid >> 5, lane = tid & 31;
    const int wy   = wid >> 2, wx = wid & 3;
    const int m0   = wy * 64,  n0 = wx * 32;
    const int mbase = blockIdx.y * BM;
    const int nbase = blockIdx.x * BN;

    if (tid < BN) s_csq[tid] = g_cbsq[nbase + tid];

    float acc[4][4][4];
    #pragma unroll
    for (int i = 0; i < 4; i++)
        #pragma unroll
        for (int j = 0; j < 4; j++)
            #pragma unroll
            for (int q = 0; q < 4; q++) acc[i][j][q] = 0.f;

    // ldmatrix lane addressing (byte offsets) — proven R3/R4 mapping
    const int a_row  = (lane & 7) + ((lane >> 3) & 1) * 8;
    const int a_colb = (lane >> 4) * 16;
    const int b_row  = (lane & 7) + (lane >> 4) * 8;
    const int b_colb = ((lane >> 3) & 1) * 16;

    uint32_t aBase[NSTAGE], bBase[NSTAGE];
    #pragma unroll
    for (int s = 0; s < NSTAGE; s++) {
        aBase[s] = sb + s * STGB + (uint32_t)((m0 + a_row) * ROWPB + a_colb);
        bBase[s] = sb + s * STGB + ASZB + (uint32_t)((n0 + b_row) * ROWPB + b_colb);
    }

    // loader: A 128 rows x 128B, B 128 rows x 128B; 2 threads/row, 64B each
    const int ld_row = tid >> 1;
    const int ld_off = (tid & 1) * 64;
    auto load_chunk = [&](int s, int cc) {
        const uint32_t soA = sb + s * STGB + (uint32_t)(ld_row * ROWPB + ld_off);
        const uint32_t soB = soA + ASZB;
        const __nv_bfloat16* gA = g_xb + (size_t)(mbase + ld_row) * C_DIM + cc + ld_off / 2;
        const __nv_bfloat16* gB = g_cbb + (size_t)(nbase + ld_row) * C_DIM + cc + ld_off / 2;
        #pragma unroll
        for (int q = 0; q < 4; q++) {
            cpasync16(soA + q * 16, gA + q * 8);
            cpasync16(soB + q * 16, gB + q * 8);
        }
    };

    load_chunk(0, 0); CP_COMMIT();
    load_chunk(1, BK); CP_COMMIT();

    #pragma unroll
    for (int ch = 0; ch < NCHUNK; ch++) {
        if (ch < NCHUNK - 1) { CP_WAIT(1); } else { CP_WAIT(0); }
        __syncthreads();
        if (ch + 2 < NCHUNK) { load_chunk((ch + 2) % NSTAGE, (ch + 2) * BK); CP_COMMIT(); }

        const uint32_t aS = aBase[ch % NSTAGE], bS = bBase[ch % NSTAGE];
        #pragma unroll
        for (int ks = 0; ks < 4; ks++) {            // four k16 steps per chunk
            uint32_t a[4][4];
            #pragma unroll
            for (int mf = 0; mf < 4; mf++)
                ldsm4(a[mf], aS + (uint32_t)(mf * 16 * ROWPB) + ks * 32);
            uint32_t b[4][2];
            #pragma unroll
            for (int np = 0; np < 2; np++) {
                uint32_t r[4];
                ldsm4(r, bS + (uint32_t)(np * 16 * ROWPB) + ks * 32);
                b[np * 2 + 0][0] = r[0]; b[np * 2 + 0][1] = r[1];
                b[np * 2 + 1][0] = r[2]; b[np * 2 + 1][1] = r[3];
            }
            #pragma unroll
            for (int mf = 0; mf < 4; mf++)
                #pragma unroll
                for (int nf = 0; nf < 4; nf++)
                    mma16816(acc[mf][nf], a[mf], b[nf]);
        }
    }

    // ---- epilogue: 32-bit ord-score block mins + per-row atomicMin ----
    const int qrow = lane >> 2;
    const int qcol = (lane & 3) * 2;
    #pragma unroll
    for (int mf = 0; mf < 4; mf++) {
        const int row0 = mbase + m0 + mf * 16 + qrow;
        unsigned rb0 = 0xFFFFFFFFu, rb1 = 0xFFFFFFFFu;
        #pragma unroll
        for (int nf = 0; nf < 4; nf++) {
            const int cb_loc = n0 + nf * 8 + qcol;
            const float cs0 = s_csq[cb_loc], cs1 = s_csq[cb_loc + 1];
            unsigned u0 = umin2(f2ord(fmaf(2.f, acc[mf][nf][0], cs0)),
                                f2ord(fmaf(2.f, acc[mf][nf][1], cs1)));
            unsigned u1 = umin2(f2ord(fmaf(2.f, acc[mf][nf][2], cs0)),
                                f2ord(fmaf(2.f, acc[mf][nf][3], cs1)));
            #pragma unroll
            for (int o = 1; o <= 2; o <<= 1) {
                u0 = umin2(u0, __shfl_xor_sync(0xffffffffu, u0, o));
                u1 = umin2(u1, __shfl_xor_sync(0xffffffffu, u1, o));
            }
            if ((lane & 3) == 0) {
                const int blk = (nbase + n0 + nf * 8) >> 3;
                __stcs(&g_blockmin[(size_t)row0 * (K_CB / 8) + blk], u0);
                __stcs(&g_blockmin[(size_t)(row0 + 8) * (K_CB / 8) + blk], u1);
                rb0 = umin2(rb0, u0);
                rb1 = umin2(rb1, u1);
            }
        }
        if ((lane & 3) == 0) {
            atomicMin(&g_best[row0], rb0);
            atomicMin(&g_best[row0 + 8], rb1);
        }
    }
}

// ---------------------------------------------------------------------------
// Exact fp32 rescue — one warp per row; rescoring picks the exact argmin
// ---------------------------------------------------------------------------
__global__ void __launch_bounds__(256) rescue_kernel(const float* __restrict__ X,
                                                     const float* __restrict__ CB) {
    const int row = blockIdx.x * 8 + (threadIdx.x >> 5);
    const int lane = threadIdx.x & 31;

    float x[16];
    {
        const float4* xr = (const float4*)(X + (size_t)row * C_DIM + lane * 16);
        float4 a = xr[0], b = xr[1], c = xr[2], d = xr[3];
        x[0]=a.x; x[1]=a.y; x[2]=a.z; x[3]=a.w; x[4]=b.x; x[5]=b.y; x[6]=b.z; x[7]=b.w;
        x[8]=c.x; x[9]=c.y; x[10]=c.z; x[11]=c.w; x[12]=d.x; x[13]=d.y; x[14]=d.z; x[15]=d.w;
    }

    const float s1 = ord2f(g_best[row]);
    const unsigned thr = f2ord(s1 + MARGIN);

    float bests = 3.4e38f; int bestk = 0x7FFFFFFF;
    const unsigned* bm = g_blockmin + (size_t)row * (K_CB / 8);

    for (int r = 0; r < 32; r++) {
        unsigned v = __ldcs(&bm[r * 32 + lane]);
        unsigned mask = __ballot_sync(0xffffffffu, v <= thr);
        while (mask) {
            int b = __ffs(mask) - 1;
            mask &= mask - 1;
            int k0 = (r * 32 + b) * 8;
            #pragma unroll
            for (int j = 0; j < 8; j++) {
                int k = k0 + j;
                const float4* cr = (const float4*)(CB + (size_t)k * C_DIM + lane * 16);
                float4 c0 = cr[0], c1 = cr[1], c2 = cr[2], c3 = cr[3];
                float p = 0.f;
                p = fmaf(x[0],  c0.x, p); p = fmaf(x[1],  c0.y, p);
                p = fmaf(x[2],  c0.z, p); p = fmaf(x[3],  c0.w, p);
                p = fmaf(x[4],  c1.x, p); p = fmaf(x[5],  c1.y, p);
                p = fmaf(x[6],  c1.z, p); p = fmaf(x[7],  c1.w, p);
                p = fmaf(x[8],  c2.x, p); p = fmaf(x[9],  c2.y, p);
                p = fmaf(x[10], c2.z, p); p = fmaf(x[11], c2.w, p);
                p = fmaf(x[12], c3.x, p); p = fmaf(x[13], c3.y, p);
                p = fmaf(x[14], c3.z, p); p = fmaf(x[15], c3.w, p);
                #pragma unroll
                for (int o = 16; o; o >>= 1) p += __shfl_xor_sync(0xffffffffu, p, o);
                float s = fmaf(2.f, p, __ldg(&g_cbsq[k]));
                if (s < bests || (s == bests && k < bestk)) { bests = s; bestk = k; }
            }
        }
    }
    if (lane == 0) g_bestk[row] = bestk;
}

// ---------------------------------------------------------------------------
__global__ void gather_kernel(const float* __restrict__ CB,
                              float* __restrict__ out, int out_size) {
    const int row = blockIdx.x;
    const int k = g_bestk[row];
    const size_t BNC = (size_t)M_TOTAL * C_DIM;

    float4 v = ((const float4*)(CB + (size_t)k * C_DIM))[threadIdx.x];
    ((float4*)(out + (size_t)row * C_DIM))[threadIdx.x] = v;
    if ((size_t)out_size >= 2 * BNC)
        ((float4*)(out + BNC + (size_t)row * C_DIM))[threadIdx.x] = v;
    if (threadIdx.x == 0 && (size_t)out_size >= 2 * BNC + M_TOTAL)
        out[2 * BNC + row] = (float)k;
}

// ---------------------------------------------------------------------------
extern "C" void kernel_launch(void* const* d_in, const int* in_sizes, int n_in,
                              void* d_out, int out_size) {
    const float* X  = (const float*)d_in[0];
    const float* CB = (const float*)d_in[1];
    if (n_in >= 2 && in_sizes[0] == K_CB * C_DIM && in_sizes[1] == M_TOTAL * C_DIM) {
        X  = (const float*)d_in[1];
        CB = (const float*)d_in[0];
    }
    float* out = (float*)d_out;

    static bool attr_set = false;
    if (!attr_set) {
        cudaFuncSetAttribute(gemm_kernel, cudaFuncAttributeMaxDynamicSharedMemorySize, SMEM_TOTAL);
        attr_set = true;
    }

    const long nconv = ((long)M_TOTAL * C_DIM + (long)K_CB * C_DIM) / 4;
    convert_kernel<<<(unsigned)((nconv + 255) / 256), 256>>>(X, CB);
    cbsq_kernel<<<K_CB / 8, 256>>>(CB);
    init_kernel<<<(M_TOTAL + 255) / 256, 256>>>();
    gemm_kernel<<<dim3(K_CB / BN, M_TOTAL / BM), 256, SMEM_TOTAL>>>();
    rescue_kernel<<<M_TOTAL / 8, 256>>>(X, CB);
    gather_kernel<<<M_TOTAL, 128>>>(CB, out, out_size);
}

// round 9
// speedup vs baseline: 1.2461x; 1.1301x over previous
#include <cuda_runtime.h>
#include <cuda_bf16.h>
#include <cstdint>

// Problem constants: B=8, N=4096, C=512, K=8192
#define M_TOTAL 32768
#define K_CB    8192
#define C_DIM   512

#define BM 128
#define BN 128
#define BK 32                       // bf16 elems per chunk (64B per row)
#define NCHUNK (C_DIM / BK)         // 16
#define NSTAGE 4
#define ROWP 40                     // smem pitch in bf16 elems (80B) -> conflict-free
#define MARGIN 4.0f

#define ASZB ((BM * ROWP) * 2)      // 10240 bytes per A stage
#define BSZB ((BN * ROWP) * 2)      // 10240 bytes per B stage
#define BOFF (NSTAGE * ASZB)        // 40960
#define CSQOFF (BOFF + NSTAGE * BSZB) // 81920
#define SMEM_TOTAL (CSQOFF + BN * 4)  // 82432

// ---------------- device scratch (allocation-free) ----------------
__device__ __nv_bfloat16 g_xb[(size_t)M_TOTAL * C_DIM];   // 32MB
__device__ __nv_bfloat16 g_cbb[(size_t)K_CB * C_DIM];     // 8MB
__device__ float         g_cbsq[K_CB];
__device__ unsigned      g_blockmin[(size_t)M_TOTAL * (K_CB / 8)]; // 128MB ord scores
__device__ int           g_bestk[M_TOTAL];

// ---------------- helpers ----------------
__device__ __forceinline__ uint32_t smem_u32(const void* p) {
    uint32_t a;
    asm("{ .reg .u64 t; cvta.to.shared.u64 t, %1; cvt.u32.u64 %0, t; }" : "=r"(a) : "l"(p));
    return a;
}
__device__ __forceinline__ void cpasync16(uint32_t s, const void* g) {
    asm volatile("{ .reg .u64 gg; cvta.to.global.u64 gg, %1; cp.async.cg.shared.global [%0], [gg], 16; }"
                 :: "r"(s), "l"(g) : "memory");
}
#define CP_COMMIT()  asm volatile("cp.async.commit_group;" ::: "memory")
#define CP_WAIT(n)   asm volatile("cp.async.wait_group %0;" :: "n"(n) : "memory")

__device__ __forceinline__ void ldsm4(uint32_t* r, uint32_t a) {
    asm volatile("ldmatrix.sync.aligned.m8n8.x4.shared.b16 {%0,%1,%2,%3}, [%4];"
                 : "=r"(r[0]), "=r"(r[1]), "=r"(r[2]), "=r"(r[3]) : "r"(a));
}
__device__ __forceinline__ void mma16816(float* d, const uint32_t* a, const uint32_t* b) {
    asm volatile("mma.sync.aligned.m16n8k16.row.col.f32.bf16.bf16.f32 "
                 "{%0,%1,%2,%3}, {%4,%5,%6,%7}, {%8,%9}, {%0,%1,%2,%3};"
                 : "+f"(d[0]), "+f"(d[1]), "+f"(d[2]), "+f"(d[3])
                 : "r"(a[0]), "r"(a[1]), "r"(a[2]), "r"(a[3]), "r"(b[0]), "r"(b[1]));
}
__device__ __forceinline__ unsigned f2ord(float f) {
    unsigned u = __float_as_uint(f);
    return (u & 0x80000000u) ? ~u : (u | 0x80000000u);
}
__device__ __forceinline__ float ord2f(unsigned o) {
    unsigned u = (o & 0x80000000u) ? (o & 0x7FFFFFFFu) : ~o;
    return __uint_as_float(u);
}
__device__ __forceinline__ unsigned umin2(unsigned a, unsigned b) { return a < b ? a : b; }

// ---------------------------------------------------------------------------
__global__ void convert_kernel(const float* __restrict__ X, const float* __restrict__ CB) {
    const long NX = (long)M_TOTAL * C_DIM / 4;
    const long NC = (long)K_CB * C_DIM / 4;
    long i = (long)blockIdx.x * blockDim.x + threadIdx.x;
    if (i < NX) {
        float4 v = ((const float4*)X)[i];
        __nv_bfloat162* o = (__nv_bfloat162*)g_xb;
        o[2 * i]     = __floats2bfloat162_rn(v.x, v.y);
        o[2 * i + 1] = __floats2bfloat162_rn(v.z, v.w);
    } else if (i < NX + NC) {
        long j = i - NX;
        float4 v = ((const float4*)CB)[j];
        __nv_bfloat162* o = (__nv_bfloat162*)g_cbb;
        o[2 * j]     = __floats2bfloat162_rn(v.x, v.y);
        o[2 * j + 1] = __floats2bfloat162_rn(v.z, v.w);
    }
}

__global__ void cbsq_kernel(const float* __restrict__ cb) {
    int row = blockIdx.x * 8 + (threadIdx.x >> 5);
    int lane = threadIdx.x & 31;
    const float* r = cb + (size_t)row * C_DIM;
    float s = 0.f;
    #pragma unroll
    for (int c = lane; c < C_DIM; c += 32) { float v = r[c]; s = fmaf(v, v, s); }
    #pragma unroll
    for (int o = 16; o; o >>= 1) s += __shfl_xor_sync(0xffffffffu, s, o);
    if (lane == 0) g_cbsq[row] = s;
}

// ---------------------------------------------------------------------------
// Coarse bf16 HMMA GEMM + per-8 block-min epilogue  (R4 mainloop, lean epilogue)
//   8 warps 2(M)x4(N), warp tile 64x32, BK=32, 4-stage cp.async, 2 CTAs/SM
// ---------------------------------------------------------------------------
__global__ void __launch_bounds__(256, 2) gemm_kernel() {
    extern __shared__ __align__(16) char smem[];
    const uint32_t sb = smem_u32(smem);
    float* s_csq = (float*)(smem + CSQOFF);

    const int tid  = threadIdx.x;
    const int wid  = tid >> 5, lane = tid & 31;
    const int wy   = wid >> 2, wx = wid & 3;
    const int m0   = wy * 64,  n0 = wx * 32;
    const int mbase = blockIdx.y * BM;
    const int nbase = blockIdx.x * BN;

    if (tid < BN) s_csq[tid] = g_cbsq[nbase + tid];

    float acc[4][4][4];
    #pragma unroll
    for (int i = 0; i < 4; i++)
        #pragma unroll
        for (int j = 0; j < 4; j++)
            #pragma unroll
            for (int q = 0; q < 4; q++) acc[i][j][q] = 0.f;

    // ldmatrix lane addressing
    const int a_r = (lane & 7) + ((lane >> 3) & 1) * 8;
    const int a_c = (lane >> 4) * 8;
    const int b_r = (lane & 7) + (lane >> 4) * 8;
    const int b_c = ((lane >> 3) & 1) * 8;

    uint32_t aBase[NSTAGE], bBase[NSTAGE];
    #pragma unroll
    for (int s = 0; s < NSTAGE; s++) {
        aBase[s] = sb + s * ASZB + (uint32_t)((m0 + a_r) * ROWP + a_c) * 2;
        bBase[s] = sb + BOFF + s * BSZB + (uint32_t)((n0 + b_r) * ROWP + b_c) * 2;
    }

    // cp.async loader: thread -> (row, 16B segment), 2x16B per operand
    const int ld_row = tid >> 2, ld_seg = tid & 3;
    auto load_chunk = [&](int s, int cc) {
        const uint32_t soA = sb + s * ASZB + (uint32_t)(ld_row * ROWP + ld_seg * 8) * 2;
        const uint32_t soB = sb + BOFF + s * BSZB + (uint32_t)(ld_row * ROWP + ld_seg * 8) * 2;
        const uint32_t rstep = (uint32_t)(64 * ROWP) * 2;   // +64 rows
        const size_t gstep = (size_t)64 * C_DIM;
        const __nv_bfloat16* gA = g_xb + (size_t)(mbase + ld_row) * C_DIM + cc + ld_seg * 8;
        const __nv_bfloat16* gB = g_cbb + (size_t)(nbase + ld_row) * C_DIM + cc + ld_seg * 8;
        cpasync16(soA, gA);                 cpasync16(soB, gB);
        cpasync16(soA + rstep, gA + gstep); cpasync16(soB + rstep, gB + gstep);
    };

    load_chunk(0, 0); CP_COMMIT();
    load_chunk(1, BK); CP_COMMIT();
    load_chunk(2, 2 * BK); CP_COMMIT();

    for (int cb = 0; cb < NCHUNK; cb += NSTAGE) {
        #pragma unroll
        for (int i = 0; i < NSTAGE; i++) {
            const int ch = cb + i;
            if (ch < NCHUNK - 2)      { CP_WAIT(2); }
            else if (ch == NCHUNK - 2){ CP_WAIT(1); }
            else                      { CP_WAIT(0); }
            __syncthreads();
            if (ch + 3 < NCHUNK) { load_chunk((ch + 3) & 3, (ch + 3) * BK); CP_COMMIT(); }

            const uint32_t aS = aBase[i], bS = bBase[i];
            #pragma unroll
            for (int ks = 0; ks < 2; ks++) {
                uint32_t a[4][4];
                #pragma unroll
                for (int mf = 0; mf < 4; mf++)
                    ldsm4(a[mf], aS + (uint32_t)(mf * 16 * ROWP) * 2 + ks * 32);
                uint32_t b[4][2];
                #pragma unroll
                for (int np = 0; np < 2; np++) {
                    uint32_t r[4];
                    ldsm4(r, bS + (uint32_t)(np * 16 * ROWP) * 2 + ks * 32);
                    b[np * 2 + 0][0] = r[0]; b[np * 2 + 0][1] = r[1];
                    b[np * 2 + 1][0] = r[2]; b[np * 2 + 1][1] = r[3];
                }
                #pragma unroll
                for (int mf = 0; mf < 4; mf++)
                    #pragma unroll
                    for (int nf = 0; nf < 4; nf++)
                        mma16816(acc[mf][nf], a[mf], b[nf]);
            }
        }
    }

    // ---- epilogue: 32-bit ord-score per-8-block mins ----
    const int qrow = lane >> 2;
    const int qcol = (lane & 3) * 2;
    #pragma unroll
    for (int mf = 0; mf < 4; mf++) {
        const int row0 = mbase + m0 + mf * 16 + qrow;
        #pragma unroll
        for (int nf = 0; nf < 4; nf++) {
            const int cb_loc = n0 + nf * 8 + qcol;
            const float cs0 = s_csq[cb_loc], cs1 = s_csq[cb_loc + 1];
            unsigned u0 = umin2(f2ord(fmaf(2.f, acc[mf][nf][0], cs0)),
                                f2ord(fmaf(2.f, acc[mf][nf][1], cs1)));
            unsigned u1 = umin2(f2ord(fmaf(2.f, acc[mf][nf][2], cs0)),
                                f2ord(fmaf(2.f, acc[mf][nf][3], cs1)));
            #pragma unroll
            for (int o = 1; o <= 2; o <<= 1) {
                u0 = umin2(u0, __shfl_xor_sync(0xffffffffu, u0, o));
                u1 = umin2(u1, __shfl_xor_sync(0xffffffffu, u1, o));
            }
            if ((lane & 3) == 0) {
                const int blk = (nbase + n0 + nf * 8) >> 3;
                __stcs(&g_blockmin[(size_t)row0 * (K_CB / 8) + blk], u0);
                __stcs(&g_blockmin[(size_t)(row0 + 8) * (K_CB / 8) + blk], u1);
            }
        }
    }
}

// ---------------------------------------------------------------------------
// Exact fp32 rescue — one warp per row.
// Computes the approx row-min itself (register-cached blockmin scan), then
// rescores every block within MARGIN of it in exact fp32.
// ---------------------------------------------------------------------------
__global__ void __launch_bounds__(256) rescue_kernel(const float* __restrict__ X,
                                                     const float* __restrict__ CB) {
    const int row = blockIdx.x * 8 + (threadIdx.x >> 5);
    const int lane = threadIdx.x & 31;

    float x[16];
    {
        const float4* xr = (const float4*)(X + (size_t)row * C_DIM + lane * 16);
        float4 a = xr[0], b = xr[1], c = xr[2], d = xr[3];
        x[0]=a.x; x[1]=a.y; x[2]=a.z; x[3]=a.w; x[4]=b.x; x[5]=b.y; x[6]=b.z; x[7]=b.w;
        x[8]=c.x; x[9]=c.y; x[10]=c.z; x[11]=c.w; x[12]=d.x; x[13]=d.y; x[14]=d.z; x[15]=d.w;
    }

    const unsigned* bm = g_blockmin + (size_t)row * (K_CB / 8);

    // Pass 1: cache all 1024 block-mins (32 per lane) + row min
    unsigned vloc[32];
    unsigned mymin = 0xFFFFFFFFu;
    #pragma unroll
    for (int r = 0; r < 32; r++) {
        vloc[r] = __ldcs(&bm[r * 32 + lane]);
        mymin = umin2(mymin, vloc[r]);
    }
    #pragma unroll
    for (int o = 16; o; o >>= 1)
        mymin = umin2(mymin, __shfl_xor_sync(0xffffffffu, mymin, o));
    const unsigned thr = f2ord(ord2f(mymin) + MARGIN);

    // Pass 2: exact rescore of candidate blocks
    float bests = 3.4e38f; int bestk = 0x7FFFFFFF;
    #pragma unroll 1
    for (int r = 0; r < 32; r++) {
        unsigned mask = __ballot_sync(0xffffffffu, vloc[r] <= thr);
        while (mask) {
            int b = __ffs(mask) - 1;
            mask &= mask - 1;
            int k0 = (r * 32 + b) * 8;
            #pragma unroll
            for (int j = 0; j < 8; j++) {
                int k = k0 + j;
                const float4* cr = (const float4*)(CB + (size_t)k * C_DIM + lane * 16);
                float4 c0 = cr[0], c1 = cr[1], c2 = cr[2], c3 = cr[3];
                float p = 0.f;
                p = fmaf(x[0],  c0.x, p); p = fmaf(x[1],  c0.y, p);
                p = fmaf(x[2],  c0.z, p); p = fmaf(x[3],  c0.w, p);
                p = fmaf(x[4],  c1.x, p); p = fmaf(x[5],  c1.y, p);
                p = fmaf(x[6],  c1.z, p); p = fmaf(x[7],  c1.w, p);
                p = fmaf(x[8],  c2.x, p); p = fmaf(x[9],  c2.y, p);
                p = fmaf(x[10], c2.z, p); p = fmaf(x[11], c2.w, p);
                p = fmaf(x[12], c3.x, p); p = fmaf(x[13], c3.y, p);
                p = fmaf(x[14], c3.z, p); p = fmaf(x[15], c3.w, p);
                #pragma unroll
                for (int o = 16; o; o >>= 1) p += __shfl_xor_sync(0xffffffffu, p, o);
                float s = fmaf(2.f, p, __ldg(&g_cbsq[k]));
                if (s < bests || (s == bests && k < bestk)) { bests = s; bestk = k; }
            }
        }
    }
    if (lane == 0) g_bestk[row] = bestk;
}

// ---------------------------------------------------------------------------
__global__ void gather_kernel(const float* __restrict__ CB,
                              float* __restrict__ out, int out_size) {
    const int row = blockIdx.x;
    const int k = g_bestk[row];
    const size_t BNC = (size_t)M_TOTAL * C_DIM;

    float4 v = ((const float4*)(CB + (size_t)k * C_DIM))[threadIdx.x];
    ((float4*)(out + (size_t)row * C_DIM))[threadIdx.x] = v;
    if ((size_t)out_size >= 2 * BNC)
        ((float4*)(out + BNC + (size_t)row * C_DIM))[threadIdx.x] = v;
    if (threadIdx.x == 0 && (size_t)out_size >= 2 * BNC + M_TOTAL)
        out[2 * BNC + row] = (float)k;
}

// ---------------------------------------------------------------------------
extern "C" void kernel_launch(void* const* d_in, const int* in_sizes, int n_in,
                              void* d_out, int out_size) {
    const float* X  = (const float*)d_in[0];
    const float* CB = (const float*)d_in[1];
    if (n_in >= 2 && in_sizes[0] == K_CB * C_DIM && in_sizes[1] == M_TOTAL * C_DIM) {
        X  = (const float*)d_in[1];
        CB = (const float*)d_in[0];
    }
    float* out = (float*)d_out;

    cudaFuncSetAttribute(gemm_kernel, cudaFuncAttributeMaxDynamicSharedMemorySize, SMEM_TOTAL);

    const long nconv = ((long)M_TOTAL * C_DIM + (long)K_CB * C_DIM) / 4;
    convert_kernel<<<(unsigned)((nconv + 255) / 256), 256>>>(X, CB);
    cbsq_kernel<<<K_CB / 8, 256>>>(CB);
    gemm_kernel<<<dim3(K_CB / BN, M_TOTAL / BM), 256, SMEM_TOTAL>>>();
    rescue_kernel<<<M_TOTAL / 8, 256>>>(X, CB);
    gather_kernel<<<M_TOTAL, 128>>>(CB, out, out_size);
}